// round 11
// baseline (speedup 1.0000x reference)
#include <cuda_runtime.h>
#include <cuda_fp16.h>
#include <math.h>

#define NN   1024
#define IND  256
#define ED   32
#define HID  32
#define ODIM 128
#define NE   100000

#define NB_PROJ (NE / 32)        // 3125
#define NB_CVT  1563             // emb fp32 -> fp16 (2048 elems/block)
#define KSPLIT  32               // agg k-split

// ---- scratch (device globals; no allocation allowed) ----
__device__ __half g_projh[NE * ED];      // fp16 tanh(edge_emb @ We + be)
__device__ __half g_embh[NE * ED];       // fp16 copy of edge_emb
__device__ float g_xatt[NN * HID];
__device__ float g_natt[NN * HID];
__device__ float g_value[NN * ODIM];     // neigh @ Wv + bv
__device__ float g_s1[NN * NN];          // x_att @ n_att^T, then masked scores (in-place)
__device__ float g_ws[NN * NN];          // softmax weights
__device__ float g_wep[4 * NN * ED];     // 4-way partials of weighted emb sum
__device__ float g_part[KSPLIT * NN * ODIM];  // ksplit partials of ws@value

// single-instruction MUFU tanh (sm_75+), ~2^-11 max error
__device__ __forceinline__ float fast_tanh(float x) {
    float y;
    asm("tanh.approx.f32 %0, %1;" : "=f"(y) : "f"(x));
    return y;
}

// ============================================================
// projcvt: proj[e,:] = tanh(emb[e,:] @ We + be) -> fp16
//          plus fp16 copy of emb
// ============================================================
__global__ void __launch_bounds__(256) projcvt_kernel(const float* __restrict__ emb,
                                                      const float* __restrict__ We,
                                                      const float* __restrict__ be) {
    int bid = blockIdx.x;
    if (bid < NB_PROJ) {
        __shared__ float sW[1024];
        __shared__ float sb[32];
        __shared__ __align__(16) float sx[1024];
        int tid = threadIdx.x;
        for (int i = tid; i < 1024; i += 256) sW[i] = We[i];
        if (tid < 32) sb[tid] = be[tid];
        int rows0 = bid * 32;
        reinterpret_cast<float4*>(sx)[tid] =
            reinterpret_cast<const float4*>(emb)[rows0 * 8 + tid];
        __syncthreads();
        int col = tid & 31;
        int r0 = (tid >> 5) * 4;
        float acc0 = sb[col], acc1 = acc0, acc2 = acc0, acc3 = acc0;
#pragma unroll
        for (int d = 0; d < 32; d++) {
            float w = sW[d * 32 + col];
            acc0 = fmaf(sx[(r0 + 0) * 32 + d], w, acc0);
            acc1 = fmaf(sx[(r0 + 1) * 32 + d], w, acc1);
            acc2 = fmaf(sx[(r0 + 2) * 32 + d], w, acc2);
            acc3 = fmaf(sx[(r0 + 3) * 32 + d], w, acc3);
        }
        g_projh[(rows0 + r0 + 0) * 32 + col] = __float2half(fast_tanh(acc0));
        g_projh[(rows0 + r0 + 1) * 32 + col] = __float2half(fast_tanh(acc1));
        g_projh[(rows0 + r0 + 2) * 32 + col] = __float2half(fast_tanh(acc2));
        g_projh[(rows0 + r0 + 3) * 32 + col] = __float2half(fast_tanh(acc3));
    } else {
        int blk = bid - NB_PROJ;
        int base = blk * 2048 + threadIdx.x * 8;
        if (base >= NE * ED) return;
        float4 a = *reinterpret_cast<const float4*>(emb + base);
        float4 b = *reinterpret_cast<const float4*>(emb + base + 4);
        __half2 h[4];
        h[0] = __floats2half2_rn(a.x, a.y);
        h[1] = __floats2half2_rn(a.z, a.w);
        h[2] = __floats2half2_rn(b.x, b.y);
        h[3] = __floats2half2_rn(b.z, b.w);
        *reinterpret_cast<float4*>(&g_embh[base]) = *reinterpret_cast<float4*>(h);
    }
}

// ============================================================
// attention MLPs for x and neigh (256 blocks; bid<128 -> x)
// ============================================================
__global__ void __launch_bounds__(256) att2_kernel(
    const float* __restrict__ x, const float* __restrict__ Wx1,
    const float* __restrict__ bx1, const float* __restrict__ Wx2,
    const float* __restrict__ bx2,
    const float* __restrict__ neigh, const float* __restrict__ Wn1,
    const float* __restrict__ bn1, const float* __restrict__ Wn2,
    const float* __restrict__ bn2) {
    __shared__ float sx[8][IND];
    int which = blockIdx.x >> 7;
    int blk = blockIdx.x & 127;
    const float* X  = which ? neigh : x;
    const float* W1 = which ? Wn1 : Wx1;
    const float* b1 = which ? bn1 : bx1;
    const float* W2 = which ? Wn2 : Wx2;
    const float* b2 = which ? bn2 : bx2;
    float* dst = which ? g_natt : g_xatt;

    int warp = threadIdx.x >> 5, lane = threadIdx.x & 31;
    int row = blk * 8 + warp;
    for (int d = lane; d < IND; d += 32) sx[warp][d] = X[row * IND + d];
    __syncwarp();
    float acc = b1[lane];
#pragma unroll 8
    for (int d = 0; d < IND; d++)
        acc = fmaf(sx[warp][d], W1[d * 32 + lane], acc);
    float h = fast_tanh(acc);
    float a2 = b2[lane];
#pragma unroll
    for (int j = 0; j < 32; j++)
        a2 = fmaf(__shfl_sync(0xffffffffu, h, j), W2[j * 32 + lane], a2);
    dst[row * 32 + lane] = a2;
}

// ============================================================
// fused pair of 256->128 GEMMs (128 blocks; z = bid>>6)
// ============================================================
__global__ void __launch_bounds__(256) gemm2_kernel(
    const float* __restrict__ neigh, const float* __restrict__ Wv,
    const float* __restrict__ bv,
    const float* __restrict__ x, const float* __restrict__ Wfx,
    const float* __restrict__ bfx, float* __restrict__ outp) {
    __shared__ __align__(16) float sX[16 * IND];
    __shared__ __align__(16) float sW[32 * 128];
    int z = blockIdx.x >> 6;
    int blk = blockIdx.x & 63;
    const float* X = z ? x : neigh;
    const float* W = z ? Wfx : Wv;
    const float* b = z ? bfx : bv;
    int tid = threadIdx.x;
    int r0 = blk * 16;
#pragma unroll
    for (int j = 0; j < 4; j++) {
        int f = tid + j * 256;
        int r = f >> 6, c4 = f & 63;
        reinterpret_cast<float4*>(sX)[f] =
            reinterpret_cast<const float4*>(X)[(r0 + r) * 64 + c4];
    }
    int c = tid & 127;
    int rh = tid >> 7;
    float acc[8];
    float bb = b[c];
#pragma unroll
    for (int i = 0; i < 8; i++) acc[i] = bb;

    for (int kt = 0; kt < IND; kt += 32) {
        __syncthreads();
#pragma unroll
        for (int j = 0; j < 4; j++) {
            int f = tid + j * 256;
            int rr = f >> 5, cc = f & 31;
            reinterpret_cast<float4*>(sW)[f] =
                reinterpret_cast<const float4*>(W)[(kt + rr) * 32 + cc];
        }
        __syncthreads();
#pragma unroll
        for (int d = 0; d < 32; d++) {
            float w = sW[d * 128 + c];
#pragma unroll
            for (int i = 0; i < 8; i++)
                acc[i] = fmaf(sX[(rh * 8 + i) * IND + kt + d], w, acc[i]);
        }
    }
    if (z == 0) {
#pragma unroll
        for (int i = 0; i < 8; i++) g_value[(r0 + rh * 8 + i) * ODIM + c] = acc[i];
    } else {
#pragma unroll
        for (int i = 0; i < 8; i++) outp[(r0 + rh * 8 + i) * (2 * ODIM) + c] = acc[i];
    }
}

// ============================================================
// S1 = x_att @ n_att^T   (64x32 tiles, grid (16,32))
// ============================================================
__global__ void __launch_bounds__(256) s1_kernel() {
    __shared__ __align__(16) float sA[32 * 64];
    __shared__ __align__(16) float sB[32 * 32];
    int tid = threadIdx.x;
    int bm = blockIdx.x * 64, bk = blockIdx.y * 32;
#pragma unroll
    for (int j = 0; j < 2; j++) {
        int f = tid + j * 256;
        int m = f >> 3, d4 = f & 7;
        float4 va = reinterpret_cast<const float4*>(g_xatt)[(bm + m) * 8 + d4];
        sA[(d4 * 4 + 0) * 64 + m] = va.x;
        sA[(d4 * 4 + 1) * 64 + m] = va.y;
        sA[(d4 * 4 + 2) * 64 + m] = va.z;
        sA[(d4 * 4 + 3) * 64 + m] = va.w;
    }
    {
        int m = tid >> 3, d4 = tid & 7;
        float4 vb = reinterpret_cast<const float4*>(g_natt)[(bk + m) * 8 + d4];
        sB[(d4 * 4 + 0) * 32 + m] = vb.x;
        sB[(d4 * 4 + 1) * 32 + m] = vb.y;
        sB[(d4 * 4 + 2) * 32 + m] = vb.z;
        sB[(d4 * 4 + 3) * 32 + m] = vb.w;
    }
    __syncthreads();
    int tx = tid & 15, ty = tid >> 4;
    float acc[4][2];
#pragma unroll
    for (int i = 0; i < 4; i++) { acc[i][0] = 0.f; acc[i][1] = 0.f; }
#pragma unroll
    for (int d = 0; d < 32; d++) {
        float4 a4 = *reinterpret_cast<const float4*>(&sA[d * 64 + ty * 4]);
        float b0 = sB[d * 32 + tx * 2];
        float b1 = sB[d * 32 + tx * 2 + 1];
        float a[4] = {a4.x, a4.y, a4.z, a4.w};
#pragma unroll
        for (int i = 0; i < 4; i++) {
            acc[i][0] = fmaf(a[i], b0, acc[i][0]);
            acc[i][1] = fmaf(a[i], b1, acc[i][1]);
        }
    }
#pragma unroll
    for (int i = 0; i < 4; i++) {
        g_s1[(bm + ty * 4 + i) * NN + bk + tx * 2]     = acc[i][0];
        g_s1[(bm + ty * 4 + i) * NN + bk + tx * 2 + 1] = acc[i][1];
    }
}

// ============================================================
// score: s1[n,k] += gathered proj dot -> leaky -> mask (IN-PLACE)
// 2048 blocks (row n, half h); no smem, no syncthreads
// ============================================================
__global__ void __launch_bounds__(256) score_kernel(const int* __restrict__ adj) {
    int bid = blockIdx.x;
    int n = bid >> 1, h = bid & 1;
    int tid = threadIdx.x;
    int g = tid >> 2, l4 = tid & 3;
    float xr[8];
#pragma unroll
    for (int j = 0; j < 8; j++) xr[j] = g_xatt[n * 32 + l4 * 8 + j];
    const float4* proj4 = reinterpret_cast<const float4*>(g_projh);
    int base = h * 512;
#pragma unroll
    for (int it = 0; it < 8; ++it) {
        int k = base + it * 64 + g;
        int e = adj[n * NN + k];                 // broadcast across 4 lanes
        float4 p4 = proj4[e * 4 + l4];           // 16B of the fp16 row
        const __half2* ph = reinterpret_cast<const __half2*>(&p4);
        float part = 0.f;
#pragma unroll
        for (int q = 0; q < 4; q++) {
            float2 f = __half22float2(ph[q]);
            part = fmaf(f.x, xr[2 * q], fmaf(f.y, xr[2 * q + 1], part));
        }
        part += __shfl_xor_sync(0xffffffffu, part, 1);
        part += __shfl_xor_sync(0xffffffffu, part, 2);
        if (l4 == 0) {
            float s = g_s1[n * NN + k] + part;
            s = s > 0.f ? s : 0.01f * s;         // leaky_relu(0.01)
            g_s1[n * NN + k] = (e > 0) ? s : -9e15f;
        }
    }
}

// ============================================================
// softmax per row: g_ws = softmax(g_s1)   (1024 blocks, float4/thread)
// ============================================================
__global__ void __launch_bounds__(256) softmax_kernel() {
    __shared__ float red[8];
    int n = blockIdx.x, tid = threadIdx.x;
    float4 s4 = reinterpret_cast<const float4*>(g_s1)[n * 256 + tid];
    float m = fmaxf(fmaxf(s4.x, s4.y), fmaxf(s4.z, s4.w));
#pragma unroll
    for (int o = 16; o; o >>= 1) m = fmaxf(m, __shfl_xor_sync(0xffffffffu, m, o));
    if ((tid & 31) == 0) red[tid >> 5] = m;
    __syncthreads();
    if (tid == 0) {
        float t = red[0];
        for (int i = 1; i < 8; i++) t = fmaxf(t, red[i]);
        red[0] = t;
    }
    __syncthreads();
    float M = red[0];
    __syncthreads();
    float4 e4;
    e4.x = __expf(s4.x - M); e4.y = __expf(s4.y - M);
    e4.z = __expf(s4.z - M); e4.w = __expf(s4.w - M);
    float Z = e4.x + e4.y + e4.z + e4.w;
#pragma unroll
    for (int o = 16; o; o >>= 1) Z += __shfl_xor_sync(0xffffffffu, Z, o);
    if ((tid & 31) == 0) red[tid >> 5] = Z;
    __syncthreads();
    if (tid == 0) {
        float t = 0.f;
        for (int i = 0; i < 8; i++) t += red[i];
        red[0] = t;
    }
    __syncthreads();
    float inv = 1.f / red[0];
    e4.x *= inv; e4.y *= inv; e4.z *= inv; e4.w *= inv;
    reinterpret_cast<float4*>(g_ws)[n * 256 + tid] = e4;
}

// ============================================================
// we partials: wep[q,n,:] = sum_{k in quarter q} ws[n,k]*embh[adj[n,k],:]
// 4096 blocks (n*4+q)
// ============================================================
__global__ void __launch_bounds__(256) we_kernel(const int* __restrict__ adj) {
    __shared__ __align__(16) float swe[64 * 33];
    int bid = blockIdx.x;
    int n = bid >> 2, q = bid & 3;
    int tid = threadIdx.x;
    int g = tid >> 2, l4 = tid & 3;
    const float4* emb4 = reinterpret_cast<const float4*>(g_embh);
    float acc[8];
#pragma unroll
    for (int j = 0; j < 8; j++) acc[j] = 0.f;
#pragma unroll
    for (int it = 0; it < 4; ++it) {
        int k = q * 256 + it * 64 + g;
        float w = g_ws[n * NN + k];
        int e = adj[n * NN + k];
        float4 em4 = emb4[e * 4 + l4];
        const __half2* eh = reinterpret_cast<const __half2*>(&em4);
#pragma unroll
        for (int p = 0; p < 4; p++) {
            float2 f = __half22float2(eh[p]);
            acc[2 * p]     = fmaf(w, f.x, acc[2 * p]);
            acc[2 * p + 1] = fmaf(w, f.y, acc[2 * p + 1]);
        }
    }
#pragma unroll
    for (int j = 0; j < 8; j++) swe[g * 33 + l4 * 8 + j] = acc[j];
    __syncthreads();
    if (tid < 32) {
        float a = 0.f;
#pragma unroll 8
        for (int gg = 0; gg < 64; gg++) a += swe[gg * 33 + tid];
        g_wep[(q * NN + n) * 32 + tid] = a;
    }
}

// ============================================================
// partials of ws @ value (KSPLIT=32); no epilogue
// ============================================================
#define ASTR 36
__global__ void __launch_bounds__(256) agg_kernel() {
    __shared__ __align__(16) float sA[64 * ASTR];
    __shared__ __align__(16) float sB[32 * 128];
    int tid = threadIdx.x;
    int bm = blockIdx.x * 64;
    int kz = blockIdx.y;
    int tx = tid & 15, ty = tid >> 4;
    int m0 = ty * 4;
    float acc[4][8];
#pragma unroll
    for (int i = 0; i < 4; i++)
#pragma unroll
        for (int j = 0; j < 8; j++) acc[i][j] = 0.f;

    int kt = kz * (NN / KSPLIT);
#pragma unroll
    for (int j = 0; j < 2; j++) {
        int f = tid + j * 256;
        int mm = f >> 3, c4 = f & 7;
        float4 v = reinterpret_cast<const float4*>(g_ws)[(bm + mm) * 256 + (kt >> 2) + c4];
        *reinterpret_cast<float4*>(&sA[mm * ASTR + c4 * 4]) = v;
    }
#pragma unroll
    for (int j = 0; j < 4; j++) {
        int f = tid + j * 256;
        reinterpret_cast<float4*>(sB)[f] =
            reinterpret_cast<const float4*>(g_value)[kt * 32 + f];
    }
    __syncthreads();
#pragma unroll
    for (int kk = 0; kk < 32; kk++) {
        float a0 = sA[(m0 + 0) * ASTR + kk];
        float a1 = sA[(m0 + 1) * ASTR + kk];
        float a2 = sA[(m0 + 2) * ASTR + kk];
        float a3 = sA[(m0 + 3) * ASTR + kk];
        float4 bL = *reinterpret_cast<const float4*>(&sB[kk * 128 + tx * 4]);
        float4 bH = *reinterpret_cast<const float4*>(&sB[kk * 128 + 64 + tx * 4]);
        float bb[8] = {bL.x, bL.y, bL.z, bL.w, bH.x, bH.y, bH.z, bH.w};
        float aa[4] = {a0, a1, a2, a3};
#pragma unroll
        for (int i = 0; i < 4; i++)
#pragma unroll
            for (int j = 0; j < 8; j++)
                acc[i][j] = fmaf(aa[i], bb[j], acc[i][j]);
    }

#pragma unroll
    for (int i = 0; i < 4; i++) {
        float* dst = &g_part[(kz * NN + bm + m0 + i) * ODIM];
        *reinterpret_cast<float4*>(dst + tx * 4) =
            make_float4(acc[i][0], acc[i][1], acc[i][2], acc[i][3]);
        *reinterpret_cast<float4*>(dst + 64 + tx * 4) =
            make_float4(acc[i][4], acc[i][5], acc[i][6], acc[i][7]);
    }
}

// ============================================================
// out[n,128:256] = sum_kz part + we @ Wfe + bfe   (512 blocks, 2 rows each)
// ============================================================
__global__ void __launch_bounds__(256) reduce_kernel(const float* __restrict__ bfe,
                                                     const float* __restrict__ Wfe,
                                                     float* __restrict__ outp) {
    __shared__ float swe2[2][32];
    int bid = blockIdx.x;
    int tid = threadIdx.x;
    int r = tid >> 7, c = tid & 127;
    int n0 = bid * 2;
    if (tid < 64) {
        int rr = tid >> 5, d = tid & 31;
        float a = 0.f;
#pragma unroll
        for (int q = 0; q < 4; q++) a += g_wep[(q * NN + n0 + rr) * 32 + d];
        swe2[rr][d] = a;
    }
    __syncthreads();
    int n = n0 + r;
    float v = bfe[c];
#pragma unroll
    for (int kz = 0; kz < KSPLIT; kz++)
        v += g_part[(kz * NN + n) * ODIM + c];
#pragma unroll 8
    for (int d = 0; d < 32; d++)
        v = fmaf(swe2[r][d], Wfe[d * ODIM + c], v);
    outp[n * (2 * ODIM) + ODIM + c] = v;
}

extern "C" void kernel_launch(void* const* d_in, const int* in_sizes, int n_in,
                              void* d_out, int out_size) {
    const float* x     = (const float*)d_in[0];
    const float* neigh = (const float*)d_in[1];
    const float* emb   = (const float*)d_in[2];
    const int*   adj   = (const int*)d_in[3];
    const float* Wx1 = (const float*)d_in[4];  const float* bx1 = (const float*)d_in[5];
    const float* Wx2 = (const float*)d_in[6];  const float* bx2 = (const float*)d_in[7];
    const float* Wn1 = (const float*)d_in[8];  const float* bn1 = (const float*)d_in[9];
    const float* Wn2 = (const float*)d_in[10]; const float* bn2 = (const float*)d_in[11];
    const float* We  = (const float*)d_in[12]; const float* be  = (const float*)d_in[13];
    const float* Wv  = (const float*)d_in[14]; const float* bv  = (const float*)d_in[15];
    const float* Wfe = (const float*)d_in[16]; const float* bfe = (const float*)d_in[17];
    const float* Wfx = (const float*)d_in[18]; const float* bfx = (const float*)d_in[19];
    float* out = (float*)d_out;

    cudaStream_t sB, sC, sD;
    cudaStreamCreateWithFlags(&sB, cudaStreamNonBlocking);
    cudaStreamCreateWithFlags(&sC, cudaStreamNonBlocking);
    cudaStreamCreateWithFlags(&sD, cudaStreamNonBlocking);
    cudaEvent_t evRoot, evB, evC, evS, evD;
    cudaEventCreateWithFlags(&evRoot, cudaEventDisableTiming);
    cudaEventCreateWithFlags(&evB, cudaEventDisableTiming);
    cudaEventCreateWithFlags(&evC, cudaEventDisableTiming);
    cudaEventCreateWithFlags(&evS, cudaEventDisableTiming);
    cudaEventCreateWithFlags(&evD, cudaEventDisableTiming);

    cudaEventRecord(evRoot, 0);
    cudaStreamWaitEvent(sB, evRoot, 0);
    cudaStreamWaitEvent(sC, evRoot, 0);

    // stream B: edge tables (needed by score/we)
    projcvt_kernel<<<NB_PROJ + NB_CVT, 256, 0, sB>>>(emb, We, be);
    cudaEventRecord(evB, sB);

    // stream C: value + out[:, :128] (needed by agg)
    gemm2_kernel<<<128, 256, 0, sC>>>(neigh, Wv, bv, x, Wfx, bfx, out);
    cudaEventRecord(evC, sC);

    // main: att -> s1 -> (join B) score -> softmax
    att2_kernel<<<256, 256>>>(x, Wx1, bx1, Wx2, bx2, neigh, Wn1, bn1, Wn2, bn2);
    s1_kernel<<<dim3(16, 32), 256>>>();
    cudaStreamWaitEvent(0, evB, 0);
    score_kernel<<<2048, 256>>>(adj);
    softmax_kernel<<<NN, 256>>>();
    cudaEventRecord(evS, 0);

    // stream D: weighted-emb partials, concurrent with agg
    cudaStreamWaitEvent(sD, evS, 0);
    we_kernel<<<4096, 256, 0, sD>>>(adj);
    cudaEventRecord(evD, sD);

    // main: agg (needs ws + value), then join D -> reduce
    cudaStreamWaitEvent(0, evC, 0);
    agg_kernel<<<dim3(16, KSPLIT), 256>>>();
    cudaStreamWaitEvent(0, evD, 0);
    reduce_kernel<<<512, 256>>>(bfe, Wfe, out);

    cudaEventDestroy(evRoot);
    cudaEventDestroy(evB);
    cudaEventDestroy(evC);
    cudaEventDestroy(evS);
    cudaEventDestroy(evD);
    cudaStreamDestroy(sB);
    cudaStreamDestroy(sC);
    cudaStreamDestroy(sD);
}

// round 12
// speedup vs baseline: 1.1285x; 1.1285x over previous
#include <cuda_runtime.h>
#include <cuda_fp16.h>
#include <mma.h>
#include <math.h>

#define NN   1024
#define IND  256
#define ED   32
#define HID  32
#define ODIM 128
#define NE   100000

#define NB_PROJ (NE / 32)        // 3125
#define NB_CVT  1563             // emb fp32 -> fp16 (2048 elems/block)
#define AGG_KS  8                // agg k-split

// ---- scratch (device globals; no allocation allowed) ----
__device__ __half g_projh[NE * ED];      // fp16 tanh(edge_emb @ We + be)
__device__ __half g_embh[NE * ED];       // fp16 copy of edge_emb
__device__ float g_xatt[NN * HID];
__device__ float g_natt[NN * HID];
__device__ float g_value[NN * ODIM];     // neigh @ Wv + bv (fp32)
__device__ __half g_valueh[NN * ODIM];   // fp16 copy for wmma
__device__ float g_s1[NN * NN];          // x_att @ n_att^T
__device__ __half g_wsh[NN * NN];        // fp16 softmax weights (wmma A)
__device__ float g_we[NN * ED];          // ws-weighted edge embeddings
__device__ float g_part[AGG_KS * NN * ODIM];  // k-split partials of ws@value

// single-instruction MUFU tanh (sm_75+), ~2^-11 max error
__device__ __forceinline__ float fast_tanh(float x) {
    float y;
    asm("tanh.approx.f32 %0, %1;" : "=f"(y) : "f"(x));
    return y;
}

// ============================================================
// projcvt: proj[e,:] = tanh(emb[e,:] @ We + be) -> fp16, plus fp16 emb copy
// ============================================================
__global__ void __launch_bounds__(256) projcvt_kernel(const float* __restrict__ emb,
                                                      const float* __restrict__ We,
                                                      const float* __restrict__ be) {
    int bid = blockIdx.x;
    if (bid < NB_PROJ) {
        __shared__ float sW[1024];
        __shared__ float sb[32];
        __shared__ __align__(16) float sx[1024];
        int tid = threadIdx.x;
        for (int i = tid; i < 1024; i += 256) sW[i] = We[i];
        if (tid < 32) sb[tid] = be[tid];
        int rows0 = bid * 32;
        reinterpret_cast<float4*>(sx)[tid] =
            reinterpret_cast<const float4*>(emb)[rows0 * 8 + tid];
        __syncthreads();
        int col = tid & 31;
        int r0 = (tid >> 5) * 4;
        float acc0 = sb[col], acc1 = acc0, acc2 = acc0, acc3 = acc0;
#pragma unroll
        for (int d = 0; d < 32; d++) {
            float w = sW[d * 32 + col];
            acc0 = fmaf(sx[(r0 + 0) * 32 + d], w, acc0);
            acc1 = fmaf(sx[(r0 + 1) * 32 + d], w, acc1);
            acc2 = fmaf(sx[(r0 + 2) * 32 + d], w, acc2);
            acc3 = fmaf(sx[(r0 + 3) * 32 + d], w, acc3);
        }
        g_projh[(rows0 + r0 + 0) * 32 + col] = __float2half(fast_tanh(acc0));
        g_projh[(rows0 + r0 + 1) * 32 + col] = __float2half(fast_tanh(acc1));
        g_projh[(rows0 + r0 + 2) * 32 + col] = __float2half(fast_tanh(acc2));
        g_projh[(rows0 + r0 + 3) * 32 + col] = __float2half(fast_tanh(acc3));
    } else {
        int blk = bid - NB_PROJ;
        int base = blk * 2048 + threadIdx.x * 8;
        if (base >= NE * ED) return;
        float4 a = *reinterpret_cast<const float4*>(emb + base);
        float4 b = *reinterpret_cast<const float4*>(emb + base + 4);
        __half2 h[4];
        h[0] = __floats2half2_rn(a.x, a.y);
        h[1] = __floats2half2_rn(a.z, a.w);
        h[2] = __floats2half2_rn(b.x, b.y);
        h[3] = __floats2half2_rn(b.z, b.w);
        *reinterpret_cast<float4*>(&g_embh[base]) = *reinterpret_cast<float4*>(h);
    }
}

// ============================================================
// attention MLPs for x and neigh (256 blocks; bid<128 -> x)
// ============================================================
__global__ void __launch_bounds__(256) att2_kernel(
    const float* __restrict__ x, const float* __restrict__ Wx1,
    const float* __restrict__ bx1, const float* __restrict__ Wx2,
    const float* __restrict__ bx2,
    const float* __restrict__ neigh, const float* __restrict__ Wn1,
    const float* __restrict__ bn1, const float* __restrict__ Wn2,
    const float* __restrict__ bn2) {
    __shared__ float sx[8][IND];
    int which = blockIdx.x >> 7;
    int blk = blockIdx.x & 127;
    const float* X  = which ? neigh : x;
    const float* W1 = which ? Wn1 : Wx1;
    const float* b1 = which ? bn1 : bx1;
    const float* W2 = which ? Wn2 : Wx2;
    const float* b2 = which ? bn2 : bx2;
    float* dst = which ? g_natt : g_xatt;

    int warp = threadIdx.x >> 5, lane = threadIdx.x & 31;
    int row = blk * 8 + warp;
    for (int d = lane; d < IND; d += 32) sx[warp][d] = X[row * IND + d];
    __syncwarp();
    float acc = b1[lane];
#pragma unroll 8
    for (int d = 0; d < IND; d++)
        acc = fmaf(sx[warp][d], W1[d * 32 + lane], acc);
    float h = fast_tanh(acc);
    float a2 = b2[lane];
#pragma unroll
    for (int j = 0; j < 32; j++)
        a2 = fmaf(__shfl_sync(0xffffffffu, h, j), W2[j * 32 + lane], a2);
    dst[row * 32 + lane] = a2;
}

// ============================================================
// fused pair of 256->128 GEMMs (128 blocks; z = bid>>6)
// z=0 additionally writes fp16 value copy for wmma
// ============================================================
__global__ void __launch_bounds__(256) gemm2_kernel(
    const float* __restrict__ neigh, const float* __restrict__ Wv,
    const float* __restrict__ bv,
    const float* __restrict__ x, const float* __restrict__ Wfx,
    const float* __restrict__ bfx, float* __restrict__ outp) {
    __shared__ __align__(16) float sX[16 * IND];
    __shared__ __align__(16) float sW[32 * 128];
    int z = blockIdx.x >> 6;
    int blk = blockIdx.x & 63;
    const float* X = z ? x : neigh;
    const float* W = z ? Wfx : Wv;
    const float* b = z ? bfx : bv;
    int tid = threadIdx.x;
    int r0 = blk * 16;
#pragma unroll
    for (int j = 0; j < 4; j++) {
        int f = tid + j * 256;
        int r = f >> 6, c4 = f & 63;
        reinterpret_cast<float4*>(sX)[f] =
            reinterpret_cast<const float4*>(X)[(r0 + r) * 64 + c4];
    }
    int c = tid & 127;
    int rh = tid >> 7;
    float acc[8];
    float bb = b[c];
#pragma unroll
    for (int i = 0; i < 8; i++) acc[i] = bb;

    for (int kt = 0; kt < IND; kt += 32) {
        __syncthreads();
#pragma unroll
        for (int j = 0; j < 4; j++) {
            int f = tid + j * 256;
            int rr = f >> 5, cc = f & 31;
            reinterpret_cast<float4*>(sW)[f] =
                reinterpret_cast<const float4*>(W)[(kt + rr) * 32 + cc];
        }
        __syncthreads();
#pragma unroll
        for (int d = 0; d < 32; d++) {
            float w = sW[d * 128 + c];
#pragma unroll
            for (int i = 0; i < 8; i++)
                acc[i] = fmaf(sX[(rh * 8 + i) * IND + kt + d], w, acc[i]);
        }
    }
    if (z == 0) {
#pragma unroll
        for (int i = 0; i < 8; i++) {
            int idx = (r0 + rh * 8 + i) * ODIM + c;
            g_value[idx] = acc[i];
            g_valueh[idx] = __float2half(acc[i]);
        }
    } else {
#pragma unroll
        for (int i = 0; i < 8; i++) outp[(r0 + rh * 8 + i) * (2 * ODIM) + c] = acc[i];
    }
}

// ============================================================
// S1 = x_att @ n_att^T   (64x32 tiles, grid (16,32))
// ============================================================
__global__ void __launch_bounds__(256) s1_kernel() {
    __shared__ __align__(16) float sA[32 * 64];
    __shared__ __align__(16) float sB[32 * 32];
    int tid = threadIdx.x;
    int bm = blockIdx.x * 64, bk = blockIdx.y * 32;
#pragma unroll
    for (int j = 0; j < 2; j++) {
        int f = tid + j * 256;
        int m = f >> 3, d4 = f & 7;
        float4 va = reinterpret_cast<const float4*>(g_xatt)[(bm + m) * 8 + d4];
        sA[(d4 * 4 + 0) * 64 + m] = va.x;
        sA[(d4 * 4 + 1) * 64 + m] = va.y;
        sA[(d4 * 4 + 2) * 64 + m] = va.z;
        sA[(d4 * 4 + 3) * 64 + m] = va.w;
    }
    {
        int m = tid >> 3, d4 = tid & 7;
        float4 vb = reinterpret_cast<const float4*>(g_natt)[(bk + m) * 8 + d4];
        sB[(d4 * 4 + 0) * 32 + m] = vb.x;
        sB[(d4 * 4 + 1) * 32 + m] = vb.y;
        sB[(d4 * 4 + 2) * 32 + m] = vb.z;
        sB[(d4 * 4 + 3) * 32 + m] = vb.w;
    }
    __syncthreads();
    int tx = tid & 15, ty = tid >> 4;
    float acc[4][2];
#pragma unroll
    for (int i = 0; i < 4; i++) { acc[i][0] = 0.f; acc[i][1] = 0.f; }
#pragma unroll
    for (int d = 0; d < 32; d++) {
        float4 a4 = *reinterpret_cast<const float4*>(&sA[d * 64 + ty * 4]);
        float b0 = sB[d * 32 + tx * 2];
        float b1 = sB[d * 32 + tx * 2 + 1];
        float a[4] = {a4.x, a4.y, a4.z, a4.w};
#pragma unroll
        for (int i = 0; i < 4; i++) {
            acc[i][0] = fmaf(a[i], b0, acc[i][0]);
            acc[i][1] = fmaf(a[i], b1, acc[i][1]);
        }
    }
#pragma unroll
    for (int i = 0; i < 4; i++) {
        g_s1[(bm + ty * 4 + i) * NN + bk + tx * 2]     = acc[i][0];
        g_s1[(bm + ty * 4 + i) * NN + bk + tx * 2 + 1] = acc[i][1];
    }
}

// ============================================================
// per-row: scores -> softmax -> ws (fp16), weighted emb sum (R10 monolithic)
// ============================================================
__global__ void __launch_bounds__(256) row_kernel(const int* __restrict__ adj) {
    __shared__ int sadj[NN];
    __shared__ float ss[NN];
    __shared__ __align__(16) float sx[32];
    __shared__ float red[8];
    __shared__ __align__(16) float swe[64 * 33];

    int n = blockIdx.x;
    int tid = threadIdx.x;
    for (int k = tid; k < NN; k += 256) {
        sadj[k] = adj[n * NN + k];
        ss[k] = g_s1[n * NN + k];
    }
    if (tid < 32) sx[tid] = g_xatt[n * 32 + tid];
    __syncthreads();

    int g = tid >> 2, l4 = tid & 3;
    float xr[8];
#pragma unroll
    for (int j = 0; j < 8; j++) xr[j] = sx[l4 * 8 + j];

    const float4* proj4 = reinterpret_cast<const float4*>(g_projh);
    const float4* emb4  = reinterpret_cast<const float4*>(g_embh);

#pragma unroll 8
    for (int it = 0; it < 16; ++it) {
        int k = it * 64 + g;
        int e = sadj[k];
        float4 p4 = proj4[e * 4 + l4];
        const __half2* ph = reinterpret_cast<const __half2*>(&p4);
        float part = 0.f;
#pragma unroll
        for (int q = 0; q < 4; q++) {
            float2 f = __half22float2(ph[q]);
            part = fmaf(f.x, xr[2 * q], fmaf(f.y, xr[2 * q + 1], part));
        }
        part += __shfl_xor_sync(0xffffffffu, part, 1);
        part += __shfl_xor_sync(0xffffffffu, part, 2);
        if (l4 == 0) {
            float s = ss[k] + part;
            s = s > 0.f ? s : 0.01f * s;
            ss[k] = (e > 0) ? s : -9e15f;
        }
    }
    __syncthreads();

    float m = -3.4e38f;
    for (int k = tid; k < NN; k += 256) m = fmaxf(m, ss[k]);
#pragma unroll
    for (int o = 16; o; o >>= 1) m = fmaxf(m, __shfl_xor_sync(0xffffffffu, m, o));
    if ((tid & 31) == 0) red[tid >> 5] = m;
    __syncthreads();
    if (tid == 0) {
        float t = red[0];
        for (int i = 1; i < 8; i++) t = fmaxf(t, red[i]);
        red[0] = t;
    }
    __syncthreads();
    float M = red[0];
    __syncthreads();

    float Z = 0.f;
    for (int k = tid; k < NN; k += 256) {
        float ev = __expf(ss[k] - M);
        ss[k] = ev;
        Z += ev;
    }
#pragma unroll
    for (int o = 16; o; o >>= 1) Z += __shfl_xor_sync(0xffffffffu, Z, o);
    if ((tid & 31) == 0) red[tid >> 5] = Z;
    __syncthreads();
    if (tid == 0) {
        float t = 0.f;
        for (int i = 0; i < 8; i++) t += red[i];
        red[0] = t;
    }
    __syncthreads();
    float inv = 1.f / red[0];
    for (int k = tid; k < NN; k += 256) {
        float w = ss[k] * inv;
        ss[k] = w;
        g_wsh[n * NN + k] = __float2half(w);
    }
    __syncthreads();

    float acc[8];
#pragma unroll
    for (int j = 0; j < 8; j++) acc[j] = 0.f;
#pragma unroll 8
    for (int it = 0; it < 16; ++it) {
        int k = it * 64 + g;
        float w = ss[k];
        int e = sadj[k];
        float4 em4 = emb4[e * 4 + l4];
        const __half2* eh = reinterpret_cast<const __half2*>(&em4);
#pragma unroll
        for (int q = 0; q < 4; q++) {
            float2 f = __half22float2(eh[q]);
            acc[2 * q]     = fmaf(w, f.x, acc[2 * q]);
            acc[2 * q + 1] = fmaf(w, f.y, acc[2 * q + 1]);
        }
    }
#pragma unroll
    for (int j = 0; j < 8; j++) swe[g * 33 + l4 * 8 + j] = acc[j];
    __syncthreads();
    if (tid < 32) {
        float a = 0.f;
#pragma unroll 8
        for (int gg = 0; gg < 64; gg++) a += swe[gg * 33 + tid];
        g_we[n * 32 + tid] = a;
    }
}

// ============================================================
// wmma agg: partials of ws(fp16) @ value(fp16), fp32 accum
// tile 64m x 128n, k-split 8 (K=128 each), grid (16, 8), 256 thr (8 warps 2x4)
// ============================================================
__global__ void __launch_bounds__(256) aggw_kernel() {
    using namespace nvcuda::wmma;
    __shared__ __align__(16) __half sA[64 * 72];    // ws tile, ld=72 (144B rows)
    __shared__ __align__(16) __half sB[64 * 128];   // value tile, ld=128
    int tid = threadIdx.x;
    int bm = blockIdx.x * 64;
    int kz = blockIdx.y;
    int warp = tid >> 5;
    int wm = (warp >> 2) * 32;       // 0 or 32
    int wn = (warp & 3) * 32;        // 0,32,64,96

    fragment<accumulator, 16, 16, 16, float> acc[2][2];
#pragma unroll
    for (int i = 0; i < 2; i++)
#pragma unroll
        for (int j = 0; j < 2; j++) fill_fragment(acc[i][j], 0.f);

    for (int kt = kz * 128; kt < kz * 128 + 128; kt += 64) {
        __syncthreads();
        // stage A: 64 rows x 64 halfs (8 float4 per row)
#pragma unroll
        for (int j = 0; j < 2; j++) {
            int f = tid + j * 256;           // 0..511
            int r = f >> 3, c8 = f & 7;
            float4 v = *reinterpret_cast<const float4*>(&g_wsh[(bm + r) * NN + kt + c8 * 8]);
            *reinterpret_cast<float4*>(&sA[r * 72 + c8 * 8]) = v;
        }
        // stage B: 64 rows x 128 halfs (16 float4 per row)
#pragma unroll
        for (int j = 0; j < 4; j++) {
            int f = tid + j * 256;           // 0..1023
            int r = f >> 4, c8 = f & 15;
            float4 v = *reinterpret_cast<const float4*>(&g_valueh[(kt + r) * ODIM + c8 * 8]);
            *reinterpret_cast<float4*>(&sB[r * 128 + c8 * 8]) = v;
        }
        __syncthreads();
#pragma unroll
        for (int kk = 0; kk < 4; kk++) {
            fragment<matrix_a, 16, 16, 16, __half, row_major> a0, a1;
            load_matrix_sync(a0, &sA[(wm + 0) * 72 + kk * 16], 72);
            load_matrix_sync(a1, &sA[(wm + 16) * 72 + kk * 16], 72);
            fragment<matrix_b, 16, 16, 16, __half, row_major> b0, b1;
            load_matrix_sync(b0, &sB[kk * 16 * 128 + wn], 128);
            load_matrix_sync(b1, &sB[kk * 16 * 128 + wn + 16], 128);
            mma_sync(acc[0][0], a0, b0, acc[0][0]);
            mma_sync(acc[0][1], a0, b1, acc[0][1]);
            mma_sync(acc[1][0], a1, b0, acc[1][0]);
            mma_sync(acc[1][1], a1, b1, acc[1][1]);
        }
    }
#pragma unroll
    for (int i = 0; i < 2; i++)
#pragma unroll
        for (int j = 0; j < 2; j++)
            store_matrix_sync(&g_part[(kz * NN + bm + wm + i * 16) * ODIM + wn + j * 16],
                              acc[i][j], ODIM, mem_row_major);
}

// ============================================================
// out[n,128:256] = sum_kz part + we @ Wfe + bfe   (512 blocks, 2 rows each)
// ============================================================
__global__ void __launch_bounds__(256) reduce_kernel(const float* __restrict__ bfe,
                                                     const float* __restrict__ Wfe,
                                                     float* __restrict__ outp) {
    __shared__ float swe2[2][32];
    int bid = blockIdx.x;
    int tid = threadIdx.x;
    int r = tid >> 7, c = tid & 127;
    int n0 = bid * 2;
    if (tid < 64) {
        int rr = tid >> 5, d = tid & 31;
        swe2[rr][d] = g_we[(n0 + rr) * 32 + d];
    }
    __syncthreads();
    int n = n0 + r;
    float v = bfe[c];
#pragma unroll
    for (int kz = 0; kz < AGG_KS; kz++)
        v += g_part[(kz * NN + n) * ODIM + c];
#pragma unroll 8
    for (int d = 0; d < 32; d++)
        v = fmaf(swe2[r][d], Wfe[d * ODIM + c], v);
    outp[n * (2 * ODIM) + ODIM + c] = v;
}

extern "C" void kernel_launch(void* const* d_in, const int* in_sizes, int n_in,
                              void* d_out, int out_size) {
    const float* x     = (const float*)d_in[0];
    const float* neigh = (const float*)d_in[1];
    const float* emb   = (const float*)d_in[2];
    const int*   adj   = (const int*)d_in[3];
    const float* Wx1 = (const float*)d_in[4];  const float* bx1 = (const float*)d_in[5];
    const float* Wx2 = (const float*)d_in[6];  const float* bx2 = (const float*)d_in[7];
    const float* Wn1 = (const float*)d_in[8];  const float* bn1 = (const float*)d_in[9];
    const float* Wn2 = (const float*)d_in[10]; const float* bn2 = (const float*)d_in[11];
    const float* We  = (const float*)d_in[12]; const float* be  = (const float*)d_in[13];
    const float* Wv  = (const float*)d_in[14]; const float* bv  = (const float*)d_in[15];
    const float* Wfe = (const float*)d_in[16]; const float* bfe = (const float*)d_in[17];
    const float* Wfx = (const float*)d_in[18]; const float* bfx = (const float*)d_in[19];
    float* out = (float*)d_out;

    cudaStream_t sB, sC;
    cudaStreamCreateWithFlags(&sB, cudaStreamNonBlocking);
    cudaStreamCreateWithFlags(&sC, cudaStreamNonBlocking);
    cudaEvent_t evRoot, evB, evC;
    cudaEventCreateWithFlags(&evRoot, cudaEventDisableTiming);
    cudaEventCreateWithFlags(&evB, cudaEventDisableTiming);
    cudaEventCreateWithFlags(&evC, cudaEventDisableTiming);

    cudaEventRecord(evRoot, 0);
    cudaStreamWaitEvent(sB, evRoot, 0);
    cudaStreamWaitEvent(sC, evRoot, 0);

    // stream B: edge tables (needed by row)
    projcvt_kernel<<<NB_PROJ + NB_CVT, 256, 0, sB>>>(emb, We, be);
    cudaEventRecord(evB, sB);

    // stream C: value (fp32+fp16) + out[:, :128] (needed by aggw)
    gemm2_kernel<<<128, 256, 0, sC>>>(neigh, Wv, bv, x, Wfx, bfx, out);
    cudaEventRecord(evC, sC);

    // main: att -> s1 -> (join B) row -> (join C) aggw -> reduce
    att2_kernel<<<256, 256>>>(x, Wx1, bx1, Wx2, bx2, neigh, Wn1, bn1, Wn2, bn2);
    s1_kernel<<<dim3(16, 32), 256>>>();
    cudaStreamWaitEvent(0, evB, 0);
    row_kernel<<<NN, 256>>>(adj);
    cudaStreamWaitEvent(0, evC, 0);
    aggw_kernel<<<dim3(16, AGG_KS), 256>>>();
    reduce_kernel<<<512, 256>>>(bfe, Wfe, out);

    cudaEventDestroy(evRoot);
    cudaEventDestroy(evB);
    cudaEventDestroy(evC);
    cudaStreamDestroy(sB);
    cudaStreamDestroy(sC);
}

// round 13
// speedup vs baseline: 1.2796x; 1.1339x over previous
#include <cuda_runtime.h>
#include <cuda_fp16.h>
#include <mma.h>
#include <math.h>

#define NN   1024
#define IND  256
#define ED   32
#define HID  32
#define ODIM 128
#define NE   100000

#define NB_PROJ (NE / 32)        // 3125
#define AGG_KS  8                // agg k-split

// ---- scratch (device globals; no allocation allowed) ----
__device__ __half g_projh[NE * ED];      // fp16 tanh(edge_emb @ We + be)
__device__ __half g_embh[NE * ED];       // fp16 copy of edge_emb
__device__ float g_xatt[NN * HID];       // fp32 (row_kernel uses it)
__device__ __half g_xatth[NN * HID];     // fp16 (s1 wmma A)
__device__ __half g_natth[NN * HID];     // fp16 (s1 wmma B)
__device__ __half g_valueh[NN * ODIM];   // fp16 value for wmma
__device__ float g_s1[NN * NN];          // x_att @ n_att^T
__device__ __half g_wsh[NN * NN];        // fp16 softmax weights (wmma A)
__device__ float g_we[NN * ED];          // ws-weighted edge embeddings
__device__ float g_part[AGG_KS * NN * ODIM];  // k-split partials of ws@value

// single-instruction MUFU tanh (sm_75+), ~2^-11 max error
__device__ __forceinline__ float fast_tanh(float x) {
    float y;
    asm("tanh.approx.f32 %0, %1;" : "=f"(y) : "f"(x));
    return y;
}

// ============================================================
// projcvt: proj[e,:] = tanh(emb[e,:] @ We + be) -> fp16
//          AND fp16 emb copy written from the staged smem tile
// ============================================================
__global__ void __launch_bounds__(256) projcvt_kernel(const float* __restrict__ emb,
                                                      const float* __restrict__ We,
                                                      const float* __restrict__ be) {
    __shared__ float sW[1024];
    __shared__ float sb[32];
    __shared__ __align__(16) float sx[1024];
    int bid = blockIdx.x;
    int tid = threadIdx.x;
    for (int i = tid; i < 1024; i += 256) sW[i] = We[i];
    if (tid < 32) sb[tid] = be[tid];
    int rows0 = bid * 32;
    reinterpret_cast<float4*>(sx)[tid] =
        reinterpret_cast<const float4*>(emb)[rows0 * 8 + tid];
    __syncthreads();

    // fp16 emb copy from smem (4 halfs per thread)
    {
        int i4 = tid * 4;
        __half2 hh[2];
        hh[0] = __floats2half2_rn(sx[i4], sx[i4 + 1]);
        hh[1] = __floats2half2_rn(sx[i4 + 2], sx[i4 + 3]);
        *reinterpret_cast<float2*>(&g_embh[rows0 * 32 + i4]) =
            *reinterpret_cast<float2*>(hh);
    }

    int col = tid & 31;
    int r0 = (tid >> 5) * 4;
    float acc0 = sb[col], acc1 = acc0, acc2 = acc0, acc3 = acc0;
#pragma unroll
    for (int d = 0; d < 32; d++) {
        float w = sW[d * 32 + col];
        acc0 = fmaf(sx[(r0 + 0) * 32 + d], w, acc0);
        acc1 = fmaf(sx[(r0 + 1) * 32 + d], w, acc1);
        acc2 = fmaf(sx[(r0 + 2) * 32 + d], w, acc2);
        acc3 = fmaf(sx[(r0 + 3) * 32 + d], w, acc3);
    }
    g_projh[(rows0 + r0 + 0) * 32 + col] = __float2half(fast_tanh(acc0));
    g_projh[(rows0 + r0 + 1) * 32 + col] = __float2half(fast_tanh(acc1));
    g_projh[(rows0 + r0 + 2) * 32 + col] = __float2half(fast_tanh(acc2));
    g_projh[(rows0 + r0 + 3) * 32 + col] = __float2half(fast_tanh(acc3));
}

// ============================================================
// attention MLPs for x and neigh (256 blocks; bid<128 -> x)
// x: fp32 + fp16 outputs; neigh: fp16 only (s1 is sole consumer)
// ============================================================
__global__ void __launch_bounds__(256) att2_kernel(
    const float* __restrict__ x, const float* __restrict__ Wx1,
    const float* __restrict__ bx1, const float* __restrict__ Wx2,
    const float* __restrict__ bx2,
    const float* __restrict__ neigh, const float* __restrict__ Wn1,
    const float* __restrict__ bn1, const float* __restrict__ Wn2,
    const float* __restrict__ bn2) {
    __shared__ float sx[8][IND];
    int which = blockIdx.x >> 7;
    int blk = blockIdx.x & 127;
    const float* X  = which ? neigh : x;
    const float* W1 = which ? Wn1 : Wx1;
    const float* b1 = which ? bn1 : bx1;
    const float* W2 = which ? Wn2 : Wx2;
    const float* b2 = which ? bn2 : bx2;

    int warp = threadIdx.x >> 5, lane = threadIdx.x & 31;
    int row = blk * 8 + warp;
    for (int d = lane; d < IND; d += 32) sx[warp][d] = X[row * IND + d];
    __syncwarp();
    float acc = b1[lane];
#pragma unroll 8
    for (int d = 0; d < IND; d++)
        acc = fmaf(sx[warp][d], W1[d * 32 + lane], acc);
    float h = fast_tanh(acc);
    float a2 = b2[lane];
#pragma unroll
    for (int j = 0; j < 32; j++)
        a2 = fmaf(__shfl_sync(0xffffffffu, h, j), W2[j * 32 + lane], a2);
    if (which) {
        g_natth[row * 32 + lane] = __float2half(a2);
    } else {
        g_xatt[row * 32 + lane] = a2;
        g_xatth[row * 32 + lane] = __float2half(a2);
    }
}

// ============================================================
// fused pair of 256->128 GEMMs (128 blocks; z = bid>>6)
// ============================================================
__global__ void __launch_bounds__(256) gemm2_kernel(
    const float* __restrict__ neigh, const float* __restrict__ Wv,
    const float* __restrict__ bv,
    const float* __restrict__ x, const float* __restrict__ Wfx,
    const float* __restrict__ bfx, float* __restrict__ outp) {
    __shared__ __align__(16) float sX[16 * IND];
    __shared__ __align__(16) float sW[32 * 128];
    int z = blockIdx.x >> 6;
    int blk = blockIdx.x & 63;
    const float* X = z ? x : neigh;
    const float* W = z ? Wfx : Wv;
    const float* b = z ? bfx : bv;
    int tid = threadIdx.x;
    int r0 = blk * 16;
#pragma unroll
    for (int j = 0; j < 4; j++) {
        int f = tid + j * 256;
        int r = f >> 6, c4 = f & 63;
        reinterpret_cast<float4*>(sX)[f] =
            reinterpret_cast<const float4*>(X)[(r0 + r) * 64 + c4];
    }
    int c = tid & 127;
    int rh = tid >> 7;
    float acc[8];
    float bb = b[c];
#pragma unroll
    for (int i = 0; i < 8; i++) acc[i] = bb;

    for (int kt = 0; kt < IND; kt += 32) {
        __syncthreads();
#pragma unroll
        for (int j = 0; j < 4; j++) {
            int f = tid + j * 256;
            int rr = f >> 5, cc = f & 31;
            reinterpret_cast<float4*>(sW)[f] =
                reinterpret_cast<const float4*>(W)[(kt + rr) * 32 + cc];
        }
        __syncthreads();
#pragma unroll
        for (int d = 0; d < 32; d++) {
            float w = sW[d * 128 + c];
#pragma unroll
            for (int i = 0; i < 8; i++)
                acc[i] = fmaf(sX[(rh * 8 + i) * IND + kt + d], w, acc[i]);
        }
    }
    if (z == 0) {
#pragma unroll
        for (int i = 0; i < 8; i++)
            g_valueh[(r0 + rh * 8 + i) * ODIM + c] = __float2half(acc[i]);
    } else {
#pragma unroll
        for (int i = 0; i < 8; i++) outp[(r0 + rh * 8 + i) * (2 * ODIM) + c] = acc[i];
    }
}

// ============================================================
// s1 wmma: g_s1 = xatt_h @ natt_h^T  (1024x1024x32)
// 64x64 per block, grid (16,16); 8 warps: 2 m-groups x 4 n-cols
// fragments loaded directly from global
// ============================================================
__global__ void __launch_bounds__(256) s1w_kernel() {
    using namespace nvcuda::wmma;
    int bm = blockIdx.x * 64, bk = blockIdx.y * 64;
    int warp = threadIdx.x >> 5;
    int wm = bm + (warp >> 2) * 32;
    int wn = bk + (warp & 3) * 16;
    fragment<accumulator, 16, 16, 16, float> acc0, acc1;
    fill_fragment(acc0, 0.f);
    fill_fragment(acc1, 0.f);
    fragment<matrix_a, 16, 16, 16, __half, row_major> a;
    fragment<matrix_b, 16, 16, 16, __half, col_major> b;
#pragma unroll
    for (int kk = 0; kk < 2; kk++) {
        load_matrix_sync(b, g_natth + wn * 32 + kk * 16, 32);
        load_matrix_sync(a, g_xatth + wm * 32 + kk * 16, 32);
        mma_sync(acc0, a, b, acc0);
        load_matrix_sync(a, g_xatth + (wm + 16) * 32 + kk * 16, 32);
        mma_sync(acc1, a, b, acc1);
    }
    store_matrix_sync(&g_s1[wm * NN + wn], acc0, NN, mem_row_major);
    store_matrix_sync(&g_s1[(wm + 16) * NN + wn], acc1, NN, mem_row_major);
}

// ============================================================
// per-row: scores -> softmax -> ws (fp16), weighted emb sum
// ============================================================
__global__ void __launch_bounds__(256) row_kernel(const int* __restrict__ adj) {
    __shared__ int sadj[NN];
    __shared__ float ss[NN];
    __shared__ __align__(16) float sx[32];
    __shared__ float red[8];
    __shared__ __align__(16) float swe[64 * 33];

    int n = blockIdx.x;
    int tid = threadIdx.x;
    for (int k = tid; k < NN; k += 256) {
        sadj[k] = adj[n * NN + k];
        ss[k] = g_s1[n * NN + k];
    }
    if (tid < 32) sx[tid] = g_xatt[n * 32 + tid];
    __syncthreads();

    int g = tid >> 2, l4 = tid & 3;
    float xr[8];
#pragma unroll
    for (int j = 0; j < 8; j++) xr[j] = sx[l4 * 8 + j];

    const float4* proj4 = reinterpret_cast<const float4*>(g_projh);
    const float4* emb4  = reinterpret_cast<const float4*>(g_embh);

#pragma unroll 8
    for (int it = 0; it < 16; ++it) {
        int k = it * 64 + g;
        int e = sadj[k];
        float4 p4 = proj4[e * 4 + l4];
        const __half2* ph = reinterpret_cast<const __half2*>(&p4);
        float part = 0.f;
#pragma unroll
        for (int q = 0; q < 4; q++) {
            float2 f = __half22float2(ph[q]);
            part = fmaf(f.x, xr[2 * q], fmaf(f.y, xr[2 * q + 1], part));
        }
        part += __shfl_xor_sync(0xffffffffu, part, 1);
        part += __shfl_xor_sync(0xffffffffu, part, 2);
        if (l4 == 0) {
            float s = ss[k] + part;
            s = s > 0.f ? s : 0.01f * s;
            ss[k] = (e > 0) ? s : -9e15f;
        }
    }
    __syncthreads();

    float m = -3.4e38f;
    for (int k = tid; k < NN; k += 256) m = fmaxf(m, ss[k]);
#pragma unroll
    for (int o = 16; o; o >>= 1) m = fmaxf(m, __shfl_xor_sync(0xffffffffu, m, o));
    if ((tid & 31) == 0) red[tid >> 5] = m;
    __syncthreads();
    if (tid == 0) {
        float t = red[0];
        for (int i = 1; i < 8; i++) t = fmaxf(t, red[i]);
        red[0] = t;
    }
    __syncthreads();
    float M = red[0];
    __syncthreads();

    float Z = 0.f;
    for (int k = tid; k < NN; k += 256) {
        float ev = __expf(ss[k] - M);
        ss[k] = ev;
        Z += ev;
    }
#pragma unroll
    for (int o = 16; o; o >>= 1) Z += __shfl_xor_sync(0xffffffffu, Z, o);
    if ((tid & 31) == 0) red[tid >> 5] = Z;
    __syncthreads();
    if (tid == 0) {
        float t = 0.f;
        for (int i = 0; i < 8; i++) t += red[i];
        red[0] = t;
    }
    __syncthreads();
    float inv = 1.f / red[0];
    for (int k = tid; k < NN; k += 256) {
        float w = ss[k] * inv;
        ss[k] = w;
        g_wsh[n * NN + k] = __float2half(w);
    }
    __syncthreads();

    float acc[8];
#pragma unroll
    for (int j = 0; j < 8; j++) acc[j] = 0.f;
#pragma unroll 8
    for (int it = 0; it < 16; ++it) {
        int k = it * 64 + g;
        float w = ss[k];
        int e = sadj[k];
        float4 em4 = emb4[e * 4 + l4];
        const __half2* eh = reinterpret_cast<const __half2*>(&em4);
#pragma unroll
        for (int q = 0; q < 4; q++) {
            float2 f = __half22float2(eh[q]);
            acc[2 * q]     = fmaf(w, f.x, acc[2 * q]);
            acc[2 * q + 1] = fmaf(w, f.y, acc[2 * q + 1]);
        }
    }
#pragma unroll
    for (int j = 0; j < 8; j++) swe[g * 33 + l4 * 8 + j] = acc[j];
    __syncthreads();
    if (tid < 32) {
        float a = 0.f;
#pragma unroll 8
        for (int gg = 0; gg < 64; gg++) a += swe[gg * 33 + tid];
        g_we[n * 32 + tid] = a;
    }
}

// ============================================================
// wmma agg: partials of ws(fp16) @ value(fp16), fp32 accum
// tile 64m x 128n, k-split 8 (K=128 each), grid (16, 8)
// ============================================================
__global__ void __launch_bounds__(256) aggw_kernel() {
    using namespace nvcuda::wmma;
    __shared__ __align__(16) __half sA[64 * 72];
    __shared__ __align__(16) __half sB[64 * 128];
    int tid = threadIdx.x;
    int bm = blockIdx.x * 64;
    int kz = blockIdx.y;
    int warp = tid >> 5;
    int wm = (warp >> 2) * 32;
    int wn = (warp & 3) * 32;

    fragment<accumulator, 16, 16, 16, float> acc[2][2];
#pragma unroll
    for (int i = 0; i < 2; i++)
#pragma unroll
        for (int j = 0; j < 2; j++) fill_fragment(acc[i][j], 0.f);

    for (int kt = kz * 128; kt < kz * 128 + 128; kt += 64) {
        __syncthreads();
#pragma unroll
        for (int j = 0; j < 2; j++) {
            int f = tid + j * 256;
            int r = f >> 3, c8 = f & 7;
            float4 v = *reinterpret_cast<const float4*>(&g_wsh[(bm + r) * NN + kt + c8 * 8]);
            *reinterpret_cast<float4*>(&sA[r * 72 + c8 * 8]) = v;
        }
#pragma unroll
        for (int j = 0; j < 4; j++) {
            int f = tid + j * 256;
            int r = f >> 4, c8 = f & 15;
            float4 v = *reinterpret_cast<const float4*>(&g_valueh[(kt + r) * ODIM + c8 * 8]);
            *reinterpret_cast<float4*>(&sB[r * 128 + c8 * 8]) = v;
        }
        __syncthreads();
#pragma unroll
        for (int kk = 0; kk < 4; kk++) {
            fragment<matrix_a, 16, 16, 16, __half, row_major> a0, a1;
            load_matrix_sync(a0, &sA[(wm + 0) * 72 + kk * 16], 72);
            load_matrix_sync(a1, &sA[(wm + 16) * 72 + kk * 16], 72);
            fragment<matrix_b, 16, 16, 16, __half, row_major> b0, b1;
            load_matrix_sync(b0, &sB[kk * 16 * 128 + wn], 128);
            load_matrix_sync(b1, &sB[kk * 16 * 128 + wn + 16], 128);
            mma_sync(acc[0][0], a0, b0, acc[0][0]);
            mma_sync(acc[0][1], a0, b1, acc[0][1]);
            mma_sync(acc[1][0], a1, b0, acc[1][0]);
            mma_sync(acc[1][1], a1, b1, acc[1][1]);
        }
    }
#pragma unroll
    for (int i = 0; i < 2; i++)
#pragma unroll
        for (int j = 0; j < 2; j++)
            store_matrix_sync(&g_part[(kz * NN + bm + wm + i * 16) * ODIM + wn + j * 16],
                              acc[i][j], ODIM, mem_row_major);
}

// ============================================================
// out[n,128:256] = sum_kz part + we @ Wfe + bfe   (512 blocks, 2 rows each)
// ============================================================
__global__ void __launch_bounds__(256) reduce_kernel(const float* __restrict__ bfe,
                                                     const float* __restrict__ Wfe,
                                                     float* __restrict__ outp) {
    __shared__ float swe2[2][32];
    int bid = blockIdx.x;
    int tid = threadIdx.x;
    int r = tid >> 7, c = tid & 127;
    int n0 = bid * 2;
    if (tid < 64) {
        int rr = tid >> 5, d = tid & 31;
        swe2[rr][d] = g_we[(n0 + rr) * 32 + d];
    }
    __syncthreads();
    int n = n0 + r;
    float v = bfe[c];
#pragma unroll
    for (int kz = 0; kz < AGG_KS; kz++)
        v += g_part[(kz * NN + n) * ODIM + c];
#pragma unroll 8
    for (int d = 0; d < 32; d++)
        v = fmaf(swe2[r][d], Wfe[d * ODIM + c], v);
    outp[n * (2 * ODIM) + ODIM + c] = v;
}

extern "C" void kernel_launch(void* const* d_in, const int* in_sizes, int n_in,
                              void* d_out, int out_size) {
    const float* x     = (const float*)d_in[0];
    const float* neigh = (const float*)d_in[1];
    const float* emb   = (const float*)d_in[2];
    const int*   adj   = (const int*)d_in[3];
    const float* Wx1 = (const float*)d_in[4];  const float* bx1 = (const float*)d_in[5];
    const float* Wx2 = (const float*)d_in[6];  const float* bx2 = (const float*)d_in[7];
    const float* Wn1 = (const float*)d_in[8];  const float* bn1 = (const float*)d_in[9];
    const float* Wn2 = (const float*)d_in[10]; const float* bn2 = (const float*)d_in[11];
    const float* We  = (const float*)d_in[12]; const float* be  = (const float*)d_in[13];
    const float* Wv  = (const float*)d_in[14]; const float* bv  = (const float*)d_in[15];
    const float* Wfe = (const float*)d_in[16]; const float* bfe = (const float*)d_in[17];
    const float* Wfx = (const float*)d_in[18]; const float* bfx = (const float*)d_in[19];
    float* out = (float*)d_out;

    cudaStream_t sB, sC;
    cudaStreamCreateWithFlags(&sB, cudaStreamNonBlocking);
    cudaStreamCreateWithFlags(&sC, cudaStreamNonBlocking);
    cudaEvent_t evRoot, evB, evC;
    cudaEventCreateWithFlags(&evRoot, cudaEventDisableTiming);
    cudaEventCreateWithFlags(&evB, cudaEventDisableTiming);
    cudaEventCreateWithFlags(&evC, cudaEventDisableTiming);

    cudaEventRecord(evRoot, 0);
    cudaStreamWaitEvent(sB, evRoot, 0);
    cudaStreamWaitEvent(sC, evRoot, 0);

    // stream B: edge tables (needed by row)
    projcvt_kernel<<<NB_PROJ, 256, 0, sB>>>(emb, We, be);
    cudaEventRecord(evB, sB);

    // stream C: value (fp16) + out[:, :128] (needed by aggw)
    gemm2_kernel<<<128, 256, 0, sC>>>(neigh, Wv, bv, x, Wfx, bfx, out);
    cudaEventRecord(evC, sC);

    // main: att -> s1(wmma) -> (join B) row -> (join C) aggw -> reduce
    att2_kernel<<<256, 256>>>(x, Wx1, bx1, Wx2, bx2, neigh, Wn1, bn1, Wn2, bn2);
    s1w_kernel<<<dim3(16, 16), 256>>>();
    cudaStreamWaitEvent(0, evB, 0);
    row_kernel<<<NN, 256>>>(adj);
    cudaStreamWaitEvent(0, evC, 0);
    aggw_kernel<<<dim3(16, AGG_KS), 256>>>();
    reduce_kernel<<<512, 256>>>(bfe, Wfe, out);

    cudaEventDestroy(evRoot);
    cudaEventDestroy(evB);
    cudaEventDestroy(evC);
    cudaStreamDestroy(sB);
    cudaStreamDestroy(sC);
}